// round 6
// baseline (speedup 1.0000x reference)
#include <cuda_runtime.h>
#include <cuda_bf16.h>
#include <cuda_fp16.h>
#include <math.h>
#include <cstdint>

#define N_NODES 100000
#define N_EDGES 800000
#define HCDIM   128
#define C_DIM   64
#define N_CLS   40
#define EPS_F   1e-16f

// weight scratch (bf16 hi/lo): W0[16384] W1[16384] W2[16384] W12[8192 = 64x128 padded]
#define WOFF_0  0
#define WOFF_1  16384
#define WOFF_2  32768
#define WOFF_12 49152
#define WTOT    57344

// ---------------- static device scratch ----------------
__device__ __align__(16) float   g_hin[(size_t)N_NODES * HCDIM];
__device__ __align__(16) __half2 g_pq [(size_t)N_NODES * HCDIM];
__device__ __align__(16) float   g_t  [(size_t)N_NODES * C_DIM];   // head logits (padded 64)
__device__ __align__(16) __nv_bfloat16 g_wh[WTOT];
__device__ __align__(16) __nv_bfloat16 g_wl[WTOT];
__device__ float g_b12[64];
__device__ int g_deg[N_NODES];
__device__ int g_rowptr[N_NODES + 1];
__device__ int g_cursor[N_NODES];
__device__ int g_csrc[N_EDGES];

// ---------------- helpers ----------------
__device__ __forceinline__ uint32_t smem_to_u32(const void* p) {
    uint32_t a;
    asm("{ .reg .u64 t; cvta.to.shared.u64 t, %1; cvt.u32.u64 %0, t; }" : "=r"(a) : "l"(p));
    return a;
}
__device__ __forceinline__ void ldmatrix_x4(uint32_t* r, uint32_t addr) {
    asm volatile("ldmatrix.sync.aligned.m8n8.x4.shared.b16 {%0,%1,%2,%3}, [%4];"
        : "=r"(r[0]), "=r"(r[1]), "=r"(r[2]), "=r"(r[3]) : "r"(addr));
}
__device__ __forceinline__ void mma_bf16(float* c, const uint32_t* a, const uint32_t* b) {
    asm volatile("mma.sync.aligned.m16n8k16.row.col.f32.bf16.bf16.f32 "
        "{%0,%1,%2,%3}, {%4,%5,%6,%7}, {%8,%9}, {%0,%1,%2,%3};"
        : "+f"(c[0]), "+f"(c[1]), "+f"(c[2]), "+f"(c[3])
        : "r"(a[0]), "r"(a[1]), "r"(a[2]), "r"(a[3]), "r"(b[0]), "r"(b[1]));
}
__device__ __forceinline__ uint32_t pack_bf16(float a, float b) {
    __nv_bfloat162 p = __floats2bfloat162_rn(a, b);
    return *reinterpret_cast<uint32_t*>(&p);
}

// ---------------- CSR build + weight pre-conversion ----------------
__global__ void count_deg_convw_kernel(const int* __restrict__ dst,
                                       const float* __restrict__ W0,
                                       const float* __restrict__ W1,
                                       const float* __restrict__ W2) {
    int t = blockIdx.x * blockDim.x + threadIdx.x;
    if (t < N_EDGES) atomicAdd(&g_deg[dst[t]], 1);
    if (t < WOFF_12) {
        float v;
        if      (t < WOFF_1) v = W0[t - WOFF_0];
        else if (t < WOFF_2) v = W1[t - WOFF_1];
        else                 v = W2[t - WOFF_2];
        __nv_bfloat16 hi = __float2bfloat16_rn(v);
        g_wh[t] = hi;
        g_wl[t] = __float2bfloat16_rn(v - __bfloat162float(hi));
    }
}

// single-block chunked exclusive scan; re-zeroes g_deg for the next replay
__global__ void scan_kernel() {
    __shared__ int warp_sums[32];
    __shared__ int sCarry;
    const int tid  = threadIdx.x;       // 1024
    const int lane = tid & 31;
    const int wid  = tid >> 5;
    if (tid == 0) sCarry = 0;
    __syncthreads();
    for (int base = 0; base < N_NODES; base += 1024) {
        int idx = base + tid;
        int v = (idx < N_NODES) ? g_deg[idx] : 0;
        if (idx < N_NODES) g_deg[idx] = 0;
        int incl = v;
        #pragma unroll
        for (int d = 1; d < 32; d <<= 1) {
            int t = __shfl_up_sync(0xffffffffu, incl, d);
            if (lane >= d) incl += t;
        }
        if (lane == 31) warp_sums[wid] = incl;
        __syncthreads();
        if (wid == 0) {
            int s = warp_sums[lane];
            #pragma unroll
            for (int d = 1; d < 32; d <<= 1) {
                int t = __shfl_up_sync(0xffffffffu, s, d);
                if (lane >= d) s += t;
            }
            warp_sums[lane] = s;
        }
        __syncthreads();
        int carry = sCarry;
        int woff  = (wid > 0) ? warp_sums[wid - 1] : 0;
        int excl  = carry + woff + incl - v;
        if (idx < N_NODES) { g_rowptr[idx] = excl; g_cursor[idx] = excl; }
        __syncthreads();
        if (tid == 0) sCarry = carry + warp_sums[31];
        __syncthreads();
    }
    if (tid == 0) g_rowptr[N_NODES] = N_EDGES;
}

__global__ void scatter_kernel(const int* __restrict__ src, const int* __restrict__ dst) {
    int e = blockIdx.x * blockDim.x + threadIdx.x;
    if (e < N_EDGES) {
        int d   = dst[e];
        int pos = atomicAdd(&g_cursor[d], 1);
        g_csrc[pos] = src[e];
    }
}

// ---------------- head weight fold: W12 = Wp2 @ Wp1 [40,128] padded to 64 ----------------
__global__ void w12_prep_kernel(const float* __restrict__ Wp1, const float* __restrict__ bp1,
                                const float* __restrict__ Wp2, const float* __restrict__ bp2) {
    __shared__ float wp2s[N_CLS * C_DIM];    // 10 KB
    const int tid = threadIdx.x;             // 256
    for (int i = tid; i < N_CLS * C_DIM; i += 256) wp2s[i] = Wp2[i];
    __syncthreads();
    for (int idx = tid; idx < 64 * 128; idx += 256) {
        int o = idx >> 7, k = idx & 127;
        float v = 0.f;
        if (o < N_CLS) {
            #pragma unroll 8
            for (int c = 0; c < C_DIM; c++)
                v += wp2s[o * C_DIM + c] * Wp1[c * 128 + k];
        }
        __nv_bfloat16 hi = __float2bfloat16_rn(v);
        g_wh[WOFF_12 + idx] = hi;
        g_wl[WOFF_12 + idx] = __float2bfloat16_rn(v - __bfloat162float(hi));
    }
    if (tid < 64) {
        float b = 0.f;
        if (tid < N_CLS) {
            for (int c = 0; c < C_DIM; c++) b += wp2s[tid * C_DIM + c] * bp1[c];
            b += bp2[tid];
        }
        g_b12[tid] = b;
    }
}

// ---------------- HMMA split-bf16 GEMM, BM=64, B via ldmatrix.x4 ----------------
template <int BN, bool PQ_MODE>
__global__ void __launch_bounds__(256, 2) hmma_gemm(
    const float* __restrict__ A,
    const __nv_bfloat16* __restrict__ wh, const __nv_bfloat16* __restrict__ wl,
    const float* __restrict__ bias, const float* __restrict__ al,
    float* __restrict__ Out)
{
    constexpr int LD = 136;
    constexpr int NT = BN / 16;           // n8-tiles per warp
    constexpr int NP = NT / 2;            // n8-tile pairs per warp
    extern __shared__ char smem[];
    const uint32_t su = smem_to_u32(smem);
    const uint32_t OFF_AH = 0;
    const uint32_t OFF_AL = 64 * LD * 2;
    const uint32_t OFF_BH = OFF_AL + 64 * LD * 2;
    const uint32_t OFF_BL = OFF_BH + BN * LD * 2;

    const int tid  = threadIdx.x;
    const int warp = tid >> 5;
    const int lane = tid & 31;
    const int warp_r = warp & 3;
    const int warp_c = warp >> 2;
    const int rowBase = blockIdx.x * 64;

    // ---- stage A (64 rows fp32 -> bf16 hi/lo) ----
    #pragma unroll
    for (int it = 0; it < 8; it++) {
        int i = tid + it * 256;
        int r = i >> 5, c = (i & 31) * 4;
        int grow = rowBase + r;
        float4 v = make_float4(0.f, 0.f, 0.f, 0.f);
        if (grow < N_NODES) v = *(const float4*)(A + (size_t)grow * 128 + c);
        float hx = __bfloat162float(__float2bfloat16_rn(v.x));
        float hy = __bfloat162float(__float2bfloat16_rn(v.y));
        float hz = __bfloat162float(__float2bfloat16_rn(v.z));
        float hw = __bfloat162float(__float2bfloat16_rn(v.w));
        uint2 hi = make_uint2(pack_bf16(v.x, v.y), pack_bf16(v.z, v.w));
        uint2 lo = make_uint2(pack_bf16(v.x - hx, v.y - hy), pack_bf16(v.z - hz, v.w - hw));
        *(uint2*)(smem + OFF_AH + ((size_t)r * LD + c) * 2) = hi;
        *(uint2*)(smem + OFF_AL + ((size_t)r * LD + c) * 2) = lo;
    }
    // ---- stage B (preconverted bf16, pure copies) ----
    #pragma unroll
    for (int it = 0; it < BN / 16; it++) {
        int i = tid + it * 256;
        int r = i >> 4, c = (i & 15) * 8;
        uint4 vh = *(const uint4*)(wh + (size_t)r * 128 + c);
        uint4 vl = *(const uint4*)(wl + (size_t)r * 128 + c);
        *(uint4*)(smem + OFF_BH + ((size_t)r * LD + c) * 2) = vh;
        *(uint4*)(smem + OFF_BL + ((size_t)r * LD + c) * 2) = vl;
    }
    __syncthreads();

    float acc[NT][4];
    #pragma unroll
    for (int n = 0; n < NT; n++)
        #pragma unroll
        for (int j = 0; j < 4; j++) acc[n][j] = 0.f;

    const uint32_t a_lane_off =
        (uint32_t)(((warp_r * 16 + (lane & 7) + ((lane >> 3) & 1) * 8) * LD + ((lane >> 4) * 8)) * 2);
    // B x4 lane address: group g=lane>>3 -> m0=(+0,k0) m1=(+0,k0+8) m2=(+8,k0) m3=(+8,k0+8)
    const int bg = lane >> 3, br = lane & 7;
    const uint32_t b_lane_off =
        (uint32_t)(((warp_c * (BN / 2) + (bg >> 1) * 8 + br) * LD + (bg & 1) * 8) * 2);

    #pragma unroll
    for (int k0 = 0; k0 < 128; k0 += 16) {
        uint32_t ah[4], alr[4];
        ldmatrix_x4(ah,  su + OFF_AH + a_lane_off + k0 * 2);
        ldmatrix_x4(alr, su + OFF_AL + a_lane_off + k0 * 2);
        #pragma unroll
        for (int jp = 0; jp < NP; jp++) {
            uint32_t bh4[4], bl4[4];
            uint32_t boff = b_lane_off + (uint32_t)(jp * 16 * LD * 2) + k0 * 2;
            ldmatrix_x4(bh4, su + OFF_BH + boff);
            ldmatrix_x4(bl4, su + OFF_BL + boff);
            mma_bf16(acc[2*jp+0], ah,  bh4 + 0);
            mma_bf16(acc[2*jp+0], ah,  bl4 + 0);
            mma_bf16(acc[2*jp+0], alr, bh4 + 0);
            mma_bf16(acc[2*jp+1], ah,  bh4 + 2);
            mma_bf16(acc[2*jp+1], ah,  bl4 + 2);
            mma_bf16(acc[2*jp+1], alr, bh4 + 2);
        }
    }

    const int r0 = rowBase + warp_r * 16 + (lane >> 2);
    const int r1 = r0 + 8;
    #pragma unroll
    for (int n = 0; n < NT; n++) {
        const int col = warp_c * (BN / 2) + n * 8 + (lane & 3) * 2;
        const float bx = bias[col], by = bias[col + 1];
        if (PQ_MODE) {
            const float a0 = al[col], a1 = al[col + 1];
            if (r0 < N_NODES) {
                float h0v = acc[n][0] + bx, h1v = acc[n][1] + by;
                float P0 = __expf(a0 * h0v), P1 = __expf(a1 * h1v);
                __half2 x0 = __floats2half2_rn(P0, P0 * h0v);
                __half2 x1 = __floats2half2_rn(P1, P1 * h1v);
                uint2 u; u.x = *(uint32_t*)&x0; u.y = *(uint32_t*)&x1;
                *(uint2*)(g_pq + (size_t)r0 * 128 + col) = u;
            }
            if (r1 < N_NODES) {
                float h0v = acc[n][2] + bx, h1v = acc[n][3] + by;
                float P0 = __expf(a0 * h0v), P1 = __expf(a1 * h1v);
                __half2 x0 = __floats2half2_rn(P0, P0 * h0v);
                __half2 x1 = __floats2half2_rn(P1, P1 * h1v);
                uint2 u; u.x = *(uint32_t*)&x0; u.y = *(uint32_t*)&x1;
                *(uint2*)(g_pq + (size_t)r1 * 128 + col) = u;
            }
        } else {
            if (r0 < N_NODES)
                *(float2*)(Out + (size_t)r0 * BN + col) = make_float2(acc[n][0] + bx, acc[n][1] + by);
            if (r1 < N_NODES)
                *(float2*)(Out + (size_t)r1 * BN + col) = make_float2(acc[n][2] + bx, acc[n][3] + by);
        }
    }
}

// ---------------- aggregation: warp/node, coalesced index load + shfl + gather ----------
__global__ void gat_agg_sum(float* __restrict__ out) {
    const int node = blockIdx.x * (blockDim.x >> 5) + (threadIdx.x >> 5);
    if (node >= N_NODES) return;
    const int lane = threadIdx.x & 31;
    const int beg = g_rowptr[node];
    const int end = g_rowptr[node + 1];

    float S0=0.f,S1=0.f,S2=0.f,S3=0.f;
    float A0=0.f,A1=0.f,A2=0.f,A3=0.f;

    const uint4* __restrict__ pq = (const uint4*)g_pq;
    #define ACCUM(v) do { \
        __half2 p0 = *(__half2*)&(v).x, p1 = *(__half2*)&(v).y; \
        __half2 p2 = *(__half2*)&(v).z, p3 = *(__half2*)&(v).w; \
        float2 f0 = __half22float2(p0), f1 = __half22float2(p1); \
        float2 f2 = __half22float2(p2), f3 = __half22float2(p3); \
        S0 += f0.x; A0 += f0.y;  S1 += f1.x; A1 += f1.y; \
        S2 += f2.x; A2 += f2.y;  S3 += f3.x; A3 += f3.y; \
    } while (0)

    for (int base = beg; base < end; base += 32) {
        const int cnt = min(32, end - base);
        int s = (lane < cnt) ? g_csrc[base + lane] : 0;
        int i = 0;
        for (; i + 4 <= cnt; i += 4) {
            int s0 = __shfl_sync(0xffffffffu, s, i + 0);
            int s1 = __shfl_sync(0xffffffffu, s, i + 1);
            int s2 = __shfl_sync(0xffffffffu, s, i + 2);
            int s3 = __shfl_sync(0xffffffffu, s, i + 3);
            uint4 v0 = pq[(size_t)s0 * 32 + lane];
            uint4 v1 = pq[(size_t)s1 * 32 + lane];
            uint4 v2 = pq[(size_t)s2 * 32 + lane];
            uint4 v3 = pq[(size_t)s3 * 32 + lane];
            ACCUM(v0); ACCUM(v1); ACCUM(v2); ACCUM(v3);
        }
        for (; i < cnt; i++) {
            int sx = __shfl_sync(0xffffffffu, s, i);
            uint4 v = pq[(size_t)sx * 32 + lane];
            ACCUM(v);
        }
    }
    #undef ACCUM

    float4 o;
    o.x = fmaxf(A0 / (S0 + EPS_F), 0.f);
    o.y = fmaxf(A1 / (S1 + EPS_F), 0.f);
    o.z = fmaxf(A2 / (S2 + EPS_F), 0.f);
    o.w = fmaxf(A3 / (S3 + EPS_F), 0.f);
    *(float4*)(out + (size_t)node * HCDIM + lane * 4) = o;
}

// ---------------- log_softmax over 40 classes (reads padded [N,64] logits) ------------
__global__ void logsoftmax_kernel(float* __restrict__ out) {
    const int node = blockIdx.x * blockDim.x + threadIdx.x;
    if (node >= N_NODES) return;
    const float* row = g_t + (size_t)node * 64;
    float l[N_CLS];
    #pragma unroll
    for (int j = 0; j < N_CLS; j += 4) {
        float4 v = *(const float4*)(row + j);
        l[j] = v.x; l[j+1] = v.y; l[j+2] = v.z; l[j+3] = v.w;
    }
    float m = l[0];
    #pragma unroll
    for (int j = 1; j < N_CLS; j++) m = fmaxf(m, l[j]);
    float se = 0.f;
    #pragma unroll
    for (int j = 0; j < N_CLS; j++) se += __expf(l[j] - m);
    float lse = m + __logf(se);
    float* orow = out + (size_t)node * N_CLS;
    #pragma unroll
    for (int j = 0; j < N_CLS; j += 4) {
        float4 v = make_float4(l[j] - lse, l[j+1] - lse, l[j+2] - lse, l[j+3] - lse);
        *(float4*)(orow + j) = v;
    }
}

// ---------------- launch ----------------
extern "C" void kernel_launch(void* const* d_in, const int* in_sizes, int n_in,
                              void* d_out, int out_size) {
    const float* x   = (const float*)d_in[0];
    const int*   ei  = (const int*)  d_in[1];
    const float* W0  = (const float*)d_in[2];
    const float* b0  = (const float*)d_in[3];
    const float* al0 = (const float*)d_in[4];
    const float* W1  = (const float*)d_in[6];
    const float* b1  = (const float*)d_in[7];
    const float* al1 = (const float*)d_in[8];
    const float* W2  = (const float*)d_in[10];
    const float* b2  = (const float*)d_in[11];
    const float* al2 = (const float*)d_in[12];
    const float* Wp1 = (const float*)d_in[14];
    const float* bp1 = (const float*)d_in[15];
    const float* Wp2 = (const float*)d_in[16];
    const float* bp2 = (const float*)d_in[17];
    float* out = (float*)d_out;

    const int* srcv = ei;
    const int* dstv = ei + N_EDGES;

    float *hin, *tb, *b12;
    __nv_bfloat16 *wh, *wl;
    cudaGetSymbolAddress((void**)&hin, g_hin);
    cudaGetSymbolAddress((void**)&tb, g_t);
    cudaGetSymbolAddress((void**)&wh, g_wh);
    cudaGetSymbolAddress((void**)&wl, g_wl);
    cudaGetSymbolAddress((void**)&b12, g_b12);

    constexpr int LD = 136;
    const int SMEM128 = (2 * 64 * LD + 2 * 128 * LD) * 2;   // 104448
    const int SMEM64  = (2 * 64 * LD + 2 * 64  * LD) * 2;   // 69632
    cudaFuncSetAttribute((const void*)hmma_gemm<128, true>,
                         cudaFuncAttributeMaxDynamicSharedMemorySize, SMEM128);
    cudaFuncSetAttribute((const void*)hmma_gemm<64, false>,
                         cudaFuncAttributeMaxDynamicSharedMemorySize, SMEM64);

    // CSR + weight conversion
    count_deg_convw_kernel<<<(N_EDGES + 255) / 256, 256>>>(dstv, W0, W1, W2);
    scan_kernel<<<1, 1024>>>();
    scatter_kernel<<<(N_EDGES + 255) / 256, 256>>>(srcv, dstv);

    const int gemmGrid = (N_NODES + 63) / 64;     // 1563
    const int aggGrid  = (N_NODES + 7) / 8;

    // layer 0 (launch #4 -> ncu target)
    hmma_gemm<128, true><<<gemmGrid, 256, SMEM128>>>(x,   wh + WOFF_0, wl + WOFF_0, b0, al0, nullptr);
    w12_prep_kernel<<<1, 256>>>(Wp1, bp1, Wp2, bp2);
    gat_agg_sum<<<aggGrid, 256>>>(hin);
    // layer 1
    hmma_gemm<128, true><<<gemmGrid, 256, SMEM128>>>(hin, wh + WOFF_1, wl + WOFF_1, b1, al1, nullptr);
    gat_agg_sum<<<aggGrid, 256>>>(hin);
    // layer 2
    hmma_gemm<128, true><<<gemmGrid, 256, SMEM128>>>(hin, wh + WOFF_2, wl + WOFF_2, b2, al2, nullptr);
    gat_agg_sum<<<aggGrid, 256>>>(hin);
    // head: fused (Wp2@Wp1) GEMM -> padded logits, then log_softmax
    hmma_gemm<64, false><<<gemmGrid, 256, SMEM64>>>(hin, wh + WOFF_12, wl + WOFF_12, b12, nullptr, tb);
    logsoftmax_kernel<<<(N_NODES + 255) / 256, 256>>>(out);
}

// round 7
// speedup vs baseline: 1.5842x; 1.5842x over previous
#include <cuda_runtime.h>
#include <cuda_bf16.h>
#include <cuda_fp16.h>
#include <math.h>
#include <cstdint>

#define N_NODES 100000
#define N_EDGES 800000
#define HCDIM   128
#define C_DIM   64
#define N_CLS   40
#define EPS_F   1e-16f

// weight scratch (bf16 hi/lo): W0[16384] W1[16384] W2[16384] W12[8192 = 64x128 padded]
#define WOFF_0  0
#define WOFF_1  16384
#define WOFF_2  32768
#define WOFF_12 49152
#define WTOT    57344

// ---------------- static device scratch ----------------
__device__ __align__(16) float   g_hin[(size_t)N_NODES * HCDIM];
__device__ __align__(16) __half2 g_pq [(size_t)N_NODES * HCDIM];
__device__ __align__(16) float   g_t  [(size_t)N_NODES * C_DIM];   // head logits (padded 64)
__device__ __align__(16) __nv_bfloat16 g_wh[WTOT];
__device__ __align__(16) __nv_bfloat16 g_wl[WTOT];
__device__ float g_b12[64];
__device__ int g_deg[N_NODES];
__device__ int g_rowptr[N_NODES + 1];
__device__ int g_cursor[N_NODES];
__device__ int g_csrc[N_EDGES];

// ---------------- helpers ----------------
__device__ __forceinline__ uint32_t smem_to_u32(const void* p) {
    uint32_t a;
    asm("{ .reg .u64 t; cvta.to.shared.u64 t, %1; cvt.u32.u64 %0, t; }" : "=r"(a) : "l"(p));
    return a;
}
__device__ __forceinline__ void ldmatrix_x4(uint32_t* r, uint32_t addr) {
    asm volatile("ldmatrix.sync.aligned.m8n8.x4.shared.b16 {%0,%1,%2,%3}, [%4];"
        : "=r"(r[0]), "=r"(r[1]), "=r"(r[2]), "=r"(r[3]) : "r"(addr));
}
__device__ __forceinline__ void ldmatrix_x2(uint32_t* r, uint32_t addr) {
    asm volatile("ldmatrix.sync.aligned.m8n8.x2.shared.b16 {%0,%1}, [%2];"
        : "=r"(r[0]), "=r"(r[1]) : "r"(addr));
}
__device__ __forceinline__ void mma_bf16(float* c, const uint32_t* a, const uint32_t* b) {
    asm volatile("mma.sync.aligned.m16n8k16.row.col.f32.bf16.bf16.f32 "
        "{%0,%1,%2,%3}, {%4,%5,%6,%7}, {%8,%9}, {%0,%1,%2,%3};"
        : "+f"(c[0]), "+f"(c[1]), "+f"(c[2]), "+f"(c[3])
        : "r"(a[0]), "r"(a[1]), "r"(a[2]), "r"(a[3]), "r"(b[0]), "r"(b[1]));
}
__device__ __forceinline__ uint32_t pack_bf16(float a, float b) {
    __nv_bfloat162 p = __floats2bfloat162_rn(a, b);
    return *reinterpret_cast<uint32_t*>(&p);
}

// ---------------- CSR build + weight pre-conversion ----------------
__global__ void count_deg_convw_kernel(const int* __restrict__ dst,
                                       const float* __restrict__ W0,
                                       const float* __restrict__ W1,
                                       const float* __restrict__ W2) {
    int t = blockIdx.x * blockDim.x + threadIdx.x;
    if (t < N_EDGES) atomicAdd(&g_deg[dst[t]], 1);
    if (t < WOFF_12) {
        float v;
        if      (t < WOFF_1) v = W0[t - WOFF_0];
        else if (t < WOFF_2) v = W1[t - WOFF_1];
        else                 v = W2[t - WOFF_2];
        __nv_bfloat16 hi = __float2bfloat16_rn(v);
        g_wh[t] = hi;
        g_wl[t] = __float2bfloat16_rn(v - __bfloat162float(hi));
    }
}

// single-block chunked exclusive scan; re-zeroes g_deg for the next replay
__global__ void scan_kernel() {
    __shared__ int warp_sums[32];
    __shared__ int sCarry;
    const int tid  = threadIdx.x;       // 1024
    const int lane = tid & 31;
    const int wid  = tid >> 5;
    if (tid == 0) sCarry = 0;
    __syncthreads();
    for (int base = 0; base < N_NODES; base += 1024) {
        int idx = base + tid;
        int v = (idx < N_NODES) ? g_deg[idx] : 0;
        if (idx < N_NODES) g_deg[idx] = 0;
        int incl = v;
        #pragma unroll
        for (int d = 1; d < 32; d <<= 1) {
            int t = __shfl_up_sync(0xffffffffu, incl, d);
            if (lane >= d) incl += t;
        }
        if (lane == 31) warp_sums[wid] = incl;
        __syncthreads();
        if (wid == 0) {
            int s = warp_sums[lane];
            #pragma unroll
            for (int d = 1; d < 32; d <<= 1) {
                int t = __shfl_up_sync(0xffffffffu, s, d);
                if (lane >= d) s += t;
            }
            warp_sums[lane] = s;
        }
        __syncthreads();
        int carry = sCarry;
        int woff  = (wid > 0) ? warp_sums[wid - 1] : 0;
        int excl  = carry + woff + incl - v;
        if (idx < N_NODES) { g_rowptr[idx] = excl; g_cursor[idx] = excl; }
        __syncthreads();
        if (tid == 0) sCarry = carry + warp_sums[31];
        __syncthreads();
    }
    if (tid == 0) g_rowptr[N_NODES] = N_EDGES;
}

__global__ void scatter_kernel(const int* __restrict__ src, const int* __restrict__ dst) {
    int e = blockIdx.x * blockDim.x + threadIdx.x;
    if (e < N_EDGES) {
        int d   = dst[e];
        int pos = atomicAdd(&g_cursor[d], 1);
        g_csrc[pos] = src[e];
    }
}

// ---------------- head weight fold: W12 = Wp2 @ Wp1 [40,128] padded to 64 ----------------
__global__ void w12_prep_kernel(const float* __restrict__ Wp1, const float* __restrict__ bp1,
                                const float* __restrict__ Wp2, const float* __restrict__ bp2) {
    __shared__ float wp2s[N_CLS * C_DIM];    // 10 KB
    const int tid = threadIdx.x;             // 256
    for (int i = tid; i < N_CLS * C_DIM; i += 256) wp2s[i] = Wp2[i];
    __syncthreads();
    for (int idx = tid; idx < 64 * 128; idx += 256) {
        int o = idx >> 7, k = idx & 127;
        float v = 0.f;
        if (o < N_CLS) {
            #pragma unroll 8
            for (int c = 0; c < C_DIM; c++)
                v += wp2s[o * C_DIM + c] * Wp1[c * 128 + k];
        }
        __nv_bfloat16 hi = __float2bfloat16_rn(v);
        g_wh[WOFF_12 + idx] = hi;
        g_wl[WOFF_12 + idx] = __float2bfloat16_rn(v - __bfloat162float(hi));
    }
    if (tid < 64) {
        float b = 0.f;
        if (tid < N_CLS) {
            for (int c = 0; c < C_DIM; c++) b += wp2s[tid * C_DIM + c] * bp1[c];
            b += bp2[tid];
        }
        g_b12[tid] = b;
    }
}

// ---------------- HMMA split-bf16 GEMM, BM=64, warp tile 32x32 ----------------
// 8 warps: warp_r = warp&1 (two 16-row strips at rows 32*warp_r..+32),
//          warp_c = warp>>1 (cols (BN/4)*warp_c..+BN/4). B frags reused across 2 strips.
template <int BN, bool PQ_MODE>
__global__ void __launch_bounds__(256, 2) hmma_gemm(
    const float* __restrict__ A,
    const __nv_bfloat16* __restrict__ wh, const __nv_bfloat16* __restrict__ wl,
    const float* __restrict__ bias, const float* __restrict__ al,
    float* __restrict__ Out)
{
    constexpr int LD = 136;
    constexpr int CW = BN / 4;            // cols per warp
    constexpr int NT = CW / 8;            // n8-tiles per warp (4 for BN=128)
    extern __shared__ char smem[];
    const uint32_t su = smem_to_u32(smem);
    const uint32_t OFF_AH = 0;
    const uint32_t OFF_AL = 64 * LD * 2;
    const uint32_t OFF_BH = OFF_AL + 64 * LD * 2;
    const uint32_t OFF_BL = OFF_BH + BN * LD * 2;

    const int tid  = threadIdx.x;
    const int warp = tid >> 5;
    const int lane = tid & 31;
    const int warp_r = warp & 1;
    const int warp_c = warp >> 1;
    const int rowBase = blockIdx.x * 64;

    // ---- stage A (64 rows fp32 -> bf16 hi/lo) ----
    #pragma unroll
    for (int it = 0; it < 8; it++) {
        int i = tid + it * 256;
        int r = i >> 5, c = (i & 31) * 4;
        int grow = rowBase + r;
        float4 v = make_float4(0.f, 0.f, 0.f, 0.f);
        if (grow < N_NODES) v = *(const float4*)(A + (size_t)grow * 128 + c);
        float hx = __bfloat162float(__float2bfloat16_rn(v.x));
        float hy = __bfloat162float(__float2bfloat16_rn(v.y));
        float hz = __bfloat162float(__float2bfloat16_rn(v.z));
        float hw = __bfloat162float(__float2bfloat16_rn(v.w));
        uint2 hi = make_uint2(pack_bf16(v.x, v.y), pack_bf16(v.z, v.w));
        uint2 lo = make_uint2(pack_bf16(v.x - hx, v.y - hy), pack_bf16(v.z - hz, v.w - hw));
        *(uint2*)(smem + OFF_AH + ((size_t)r * LD + c) * 2) = hi;
        *(uint2*)(smem + OFF_AL + ((size_t)r * LD + c) * 2) = lo;
    }
    // ---- stage B (preconverted bf16, pure copies) ----
    #pragma unroll
    for (int it = 0; it < BN / 16; it++) {
        int i = tid + it * 256;
        int r = i >> 4, c = (i & 15) * 8;
        uint4 vh = *(const uint4*)(wh + (size_t)r * 128 + c);
        uint4 vl = *(const uint4*)(wl + (size_t)r * 128 + c);
        *(uint4*)(smem + OFF_BH + ((size_t)r * LD + c) * 2) = vh;
        *(uint4*)(smem + OFF_BL + ((size_t)r * LD + c) * 2) = vl;
    }
    __syncthreads();

    float acc[2][NT][4];
    #pragma unroll
    for (int s = 0; s < 2; s++)
        #pragma unroll
        for (int n = 0; n < NT; n++)
            #pragma unroll
            for (int j = 0; j < 4; j++) acc[s][n][j] = 0.f;

    // A fragment lane addr per 16-row strip (round-5 pattern, known good)
    uint32_t a_off[2];
    #pragma unroll
    for (int s = 0; s < 2; s++)
        a_off[s] = (uint32_t)(((warp_r * 32 + s * 16 + (lane & 7) + ((lane >> 3) & 1) * 8) * LD
                               + ((lane >> 4) * 8)) * 2);
    // B x2 lane addr (round-5 pattern, known good)
    const uint32_t b_lane_off =
        (uint32_t)(((warp_c * CW + (lane & 7)) * LD + ((lane >> 3) & 1) * 8) * 2);

    #pragma unroll
    for (int k0 = 0; k0 < 128; k0 += 16) {
        uint32_t ah0[4], al0[4], ah1[4], al1[4];
        ldmatrix_x4(ah0, su + OFF_AH + a_off[0] + k0 * 2);
        ldmatrix_x4(al0, su + OFF_AL + a_off[0] + k0 * 2);
        ldmatrix_x4(ah1, su + OFF_AH + a_off[1] + k0 * 2);
        ldmatrix_x4(al1, su + OFF_AL + a_off[1] + k0 * 2);
        #pragma unroll
        for (int n = 0; n < NT; n++) {
            uint32_t bh[2], bl[2];
            uint32_t boff = b_lane_off + (uint32_t)(n * 8 * LD * 2) + k0 * 2;
            ldmatrix_x2(bh, su + OFF_BH + boff);
            ldmatrix_x2(bl, su + OFF_BL + boff);
            mma_bf16(acc[0][n], ah0, bh);
            mma_bf16(acc[0][n], ah0, bl);
            mma_bf16(acc[0][n], al0, bh);
            mma_bf16(acc[1][n], ah1, bh);
            mma_bf16(acc[1][n], ah1, bl);
            mma_bf16(acc[1][n], al1, bh);
        }
    }

    #pragma unroll
    for (int s = 0; s < 2; s++) {
        const int r0 = rowBase + warp_r * 32 + s * 16 + (lane >> 2);
        const int r1 = r0 + 8;
        #pragma unroll
        for (int n = 0; n < NT; n++) {
            const int col = warp_c * CW + n * 8 + (lane & 3) * 2;
            const float bx = bias[col], by = bias[col + 1];
            if (PQ_MODE) {
                const float a0 = al[col], a1 = al[col + 1];
                if (r0 < N_NODES) {
                    float h0v = acc[s][n][0] + bx, h1v = acc[s][n][1] + by;
                    float P0 = __expf(a0 * h0v), P1 = __expf(a1 * h1v);
                    __half2 x0 = __floats2half2_rn(P0, P0 * h0v);
                    __half2 x1 = __floats2half2_rn(P1, P1 * h1v);
                    uint2 u; u.x = *(uint32_t*)&x0; u.y = *(uint32_t*)&x1;
                    *(uint2*)(g_pq + (size_t)r0 * 128 + col) = u;
                }
                if (r1 < N_NODES) {
                    float h0v = acc[s][n][2] + bx, h1v = acc[s][n][3] + by;
                    float P0 = __expf(a0 * h0v), P1 = __expf(a1 * h1v);
                    __half2 x0 = __floats2half2_rn(P0, P0 * h0v);
                    __half2 x1 = __floats2half2_rn(P1, P1 * h1v);
                    uint2 u; u.x = *(uint32_t*)&x0; u.y = *(uint32_t*)&x1;
                    *(uint2*)(g_pq + (size_t)r1 * 128 + col) = u;
                }
            } else {
                if (r0 < N_NODES)
                    *(float2*)(Out + (size_t)r0 * BN + col) =
                        make_float2(acc[s][n][0] + bx, acc[s][n][1] + by);
                if (r1 < N_NODES)
                    *(float2*)(Out + (size_t)r1 * BN + col) =
                        make_float2(acc[s][n][2] + bx, acc[s][n][3] + by);
            }
        }
    }
}

// ---------------- aggregation: warp/node, independent __ldg + 8-deep pipeline -----------
__global__ void gat_agg_sum(float* __restrict__ out) {
    const int node = blockIdx.x * (blockDim.x >> 5) + (threadIdx.x >> 5);
    if (node >= N_NODES) return;
    const int lane = threadIdx.x & 31;
    const int beg = g_rowptr[node];
    const int end = g_rowptr[node + 1];

    float S0=0.f,S1=0.f,S2=0.f,S3=0.f;
    float A0=0.f,A1=0.f,A2=0.f,A3=0.f;

    const uint4* __restrict__ pq = (const uint4*)g_pq;
    #define ACCUM(v) do { \
        __half2 p0 = *(__half2*)&(v).x, p1 = *(__half2*)&(v).y; \
        __half2 p2 = *(__half2*)&(v).z, p3 = *(__half2*)&(v).w; \
        float2 f0 = __half22float2(p0), f1 = __half22float2(p1); \
        float2 f2 = __half22float2(p2), f3 = __half22float2(p3); \
        S0 += f0.x; A0 += f0.y;  S1 += f1.x; A1 += f1.y; \
        S2 += f2.x; A2 += f2.y;  S3 += f3.x; A3 += f3.y; \
    } while (0)

    int e = beg;
    for (; e + 8 <= end; e += 8) {
        int s0 = __ldg(&g_csrc[e + 0]);
        int s1 = __ldg(&g_csrc[e + 1]);
        int s2 = __ldg(&g_csrc[e + 2]);
        int s3 = __ldg(&g_csrc[e + 3]);
        int s4 = __ldg(&g_csrc[e + 4]);
        int s5 = __ldg(&g_csrc[e + 5]);
        int s6 = __ldg(&g_csrc[e + 6]);
        int s7 = __ldg(&g_csrc[e + 7]);
        uint4 v0 = pq[(size_t)s0 * 32 + lane];
        uint4 v1 = pq[(size_t)s1 * 32 + lane];
        uint4 v2 = pq[(size_t)s2 * 32 + lane];
        uint4 v3 = pq[(size_t)s3 * 32 + lane];
        uint4 v4 = pq[(size_t)s4 * 32 + lane];
        uint4 v5 = pq[(size_t)s5 * 32 + lane];
        uint4 v6 = pq[(size_t)s6 * 32 + lane];
        uint4 v7 = pq[(size_t)s7 * 32 + lane];
        ACCUM(v0); ACCUM(v1); ACCUM(v2); ACCUM(v3);
        ACCUM(v4); ACCUM(v5); ACCUM(v6); ACCUM(v7);
    }
    for (; e + 2 <= end; e += 2) {
        int s0 = __ldg(&g_csrc[e + 0]);
        int s1 = __ldg(&g_csrc[e + 1]);
        uint4 v0 = pq[(size_t)s0 * 32 + lane];
        uint4 v1 = pq[(size_t)s1 * 32 + lane];
        ACCUM(v0); ACCUM(v1);
    }
    for (; e < end; e++) {
        int s = __ldg(&g_csrc[e]);
        uint4 v = pq[(size_t)s * 32 + lane];
        ACCUM(v);
    }
    #undef ACCUM

    float4 o;
    o.x = fmaxf(A0 / (S0 + EPS_F), 0.f);
    o.y = fmaxf(A1 / (S1 + EPS_F), 0.f);
    o.z = fmaxf(A2 / (S2 + EPS_F), 0.f);
    o.w = fmaxf(A3 / (S3 + EPS_F), 0.f);
    *(float4*)(out + (size_t)node * HCDIM + lane * 4) = o;
}

// ---------------- log_softmax over 40 classes (reads padded [N,64] logits) ------------
__global__ void logsoftmax_kernel(float* __restrict__ out) {
    const int node = blockIdx.x * blockDim.x + threadIdx.x;
    if (node >= N_NODES) return;
    const float* row = g_t + (size_t)node * 64;
    float l[N_CLS];
    #pragma unroll
    for (int j = 0; j < N_CLS; j += 4) {
        float4 v = *(const float4*)(row + j);
        l[j] = v.x; l[j+1] = v.y; l[j+2] = v.z; l[j+3] = v.w;
    }
    float m = l[0];
    #pragma unroll
    for (int j = 1; j < N_CLS; j++) m = fmaxf(m, l[j]);
    float se = 0.f;
    #pragma unroll
    for (int j = 0; j < N_CLS; j++) se += __expf(l[j] - m);
    float lse = m + __logf(se);
    float* orow = out + (size_t)node * N_CLS;
    #pragma unroll
    for (int j = 0; j < N_CLS; j += 4) {
        float4 v = make_float4(l[j] - lse, l[j+1] - lse, l[j+2] - lse, l[j+3] - lse);
        *(float4*)(orow + j) = v;
    }
}

// ---------------- launch ----------------
extern "C" void kernel_launch(void* const* d_in, const int* in_sizes, int n_in,
                              void* d_out, int out_size) {
    const float* x   = (const float*)d_in[0];
    const int*   ei  = (const int*)  d_in[1];
    const float* W0  = (const float*)d_in[2];
    const float* b0  = (const float*)d_in[3];
    const float* al0 = (const float*)d_in[4];
    const float* W1  = (const float*)d_in[6];
    const float* b1  = (const float*)d_in[7];
    const float* al1 = (const float*)d_in[8];
    const float* W2  = (const float*)d_in[10];
    const float* b2  = (const float*)d_in[11];
    const float* al2 = (const float*)d_in[12];
    const float* Wp1 = (const float*)d_in[14];
    const float* bp1 = (const float*)d_in[15];
    const float* Wp2 = (const float*)d_in[16];
    const float* bp2 = (const float*)d_in[17];
    float* out = (float*)d_out;

    const int* srcv = ei;
    const int* dstv = ei + N_EDGES;

    float *hin, *tb, *b12;
    __nv_bfloat16 *wh, *wl;
    cudaGetSymbolAddress((void**)&hin, g_hin);
    cudaGetSymbolAddress((void**)&tb, g_t);
    cudaGetSymbolAddress((void**)&wh, g_wh);
    cudaGetSymbolAddress((void**)&wl, g_wl);
    cudaGetSymbolAddress((void**)&b12, g_b12);

    constexpr int LD = 136;
    const int SMEM128 = (2 * 64 * LD + 2 * 128 * LD) * 2;   // 104448
    const int SMEM64  = (2 * 64 * LD + 2 * 64  * LD) * 2;   // 69632
    cudaFuncSetAttribute((const void*)hmma_gemm<128, true>,
                         cudaFuncAttributeMaxDynamicSharedMemorySize, SMEM128);
    cudaFuncSetAttribute((const void*)hmma_gemm<64, false>,
                         cudaFuncAttributeMaxDynamicSharedMemorySize, SMEM64);

    // CSR + weight conversion
    count_deg_convw_kernel<<<(N_EDGES + 255) / 256, 256>>>(dstv, W0, W1, W2);
    scan_kernel<<<1, 1024>>>();
    scatter_kernel<<<(N_EDGES + 255) / 256, 256>>>(srcv, dstv);

    const int gemmGrid = (N_NODES + 63) / 64;     // 1563
    const int aggGrid  = (N_NODES + 7) / 8;

    // layer 0 (launch #4 -> ncu target)
    hmma_gemm<128, true><<<gemmGrid, 256, SMEM128>>>(x,   wh + WOFF_0, wl + WOFF_0, b0, al0, nullptr);
    w12_prep_kernel<<<1, 256>>>(Wp1, bp1, Wp2, bp2);
    gat_agg_sum<<<aggGrid, 256>>>(hin);
    // layer 1
    hmma_gemm<128, true><<<gemmGrid, 256, SMEM128>>>(hin, wh + WOFF_1, wl + WOFF_1, b1, al1, nullptr);
    gat_agg_sum<<<aggGrid, 256>>>(hin);
    // layer 2
    hmma_gemm<128, true><<<gemmGrid, 256, SMEM128>>>(hin, wh + WOFF_2, wl + WOFF_2, b2, al2, nullptr);
    gat_agg_sum<<<aggGrid, 256>>>(hin);
    // head: fused (Wp2@Wp1) GEMM -> padded logits, then log_softmax
    hmma_gemm<64, false><<<gemmGrid, 256, SMEM64>>>(hin, wh + WOFF_12, wl + WOFF_12, b12, nullptr, tb);
    logsoftmax_kernel<<<(N_NODES + 255) / 256, 256>>>(out);
}

// round 8
// speedup vs baseline: 1.7359x; 1.0958x over previous
#include <cuda_runtime.h>
#include <cuda_bf16.h>
#include <cuda_fp16.h>
#include <math.h>
#include <cstdint>

#define N_NODES 100000
#define N_EDGES 800000
#define HCDIM   128
#define C_DIM   64
#define N_CLS   40
#define EPS_F   1e-16f

// weight scratch (bf16 hi/lo): W0[16384] W1[16384] W2[16384] W12[8192 = 64x128 padded]
#define WOFF_0  0
#define WOFF_1  16384
#define WOFF_2  32768
#define WOFF_12 49152
#define WTOT    57344

// ---------------- static device scratch ----------------
__device__ __align__(16) __nv_bfloat16 g_hb[(size_t)N_NODES * HCDIM];  // h as bf16 (exact A)
__device__ __align__(16) __half2 g_pq [(size_t)N_NODES * HCDIM];
__device__ __align__(16) float   g_t  [(size_t)N_NODES * C_DIM];       // head logits
__device__ __align__(16) __nv_bfloat16 g_wh[WTOT];
__device__ __align__(16) __nv_bfloat16 g_wl[WTOT];
__device__ float g_b12[64];
__device__ int g_deg[N_NODES];
__device__ int g_rowptr[N_NODES + 1];
__device__ int g_cursor[N_NODES];
__device__ int g_csrc[N_EDGES];

// ---------------- helpers ----------------
__device__ __forceinline__ uint32_t smem_to_u32(const void* p) {
    uint32_t a;
    asm("{ .reg .u64 t; cvta.to.shared.u64 t, %1; cvt.u32.u64 %0, t; }" : "=r"(a) : "l"(p));
    return a;
}
__device__ __forceinline__ void ldmatrix_x4(uint32_t* r, uint32_t addr) {
    asm volatile("ldmatrix.sync.aligned.m8n8.x4.shared.b16 {%0,%1,%2,%3}, [%4];"
        : "=r"(r[0]), "=r"(r[1]), "=r"(r[2]), "=r"(r[3]) : "r"(addr));
}
__device__ __forceinline__ void ldmatrix_x2(uint32_t* r, uint32_t addr) {
    asm volatile("ldmatrix.sync.aligned.m8n8.x2.shared.b16 {%0,%1}, [%2];"
        : "=r"(r[0]), "=r"(r[1]) : "r"(addr));
}
__device__ __forceinline__ void mma_bf16(float* c, const uint32_t* a, const uint32_t* b) {
    asm volatile("mma.sync.aligned.m16n8k16.row.col.f32.bf16.bf16.f32 "
        "{%0,%1,%2,%3}, {%4,%5,%6,%7}, {%8,%9}, {%0,%1,%2,%3};"
        : "+f"(c[0]), "+f"(c[1]), "+f"(c[2]), "+f"(c[3])
        : "r"(a[0]), "r"(a[1]), "r"(a[2]), "r"(a[3]), "r"(b[0]), "r"(b[1]));
}
__device__ __forceinline__ uint32_t pack_bf16(float a, float b) {
    __nv_bfloat162 p = __floats2bfloat162_rn(a, b);
    return *reinterpret_cast<uint32_t*>(&p);
}

// ---------------- CSR build + weight pre-conversion ----------------
__global__ void count_deg_convw_kernel(const int* __restrict__ dst,
                                       const float* __restrict__ W0,
                                       const float* __restrict__ W1,
                                       const float* __restrict__ W2) {
    int t = blockIdx.x * blockDim.x + threadIdx.x;
    if (t < N_EDGES) atomicAdd(&g_deg[dst[t]], 1);
    if (t < WOFF_12) {
        float v;
        if      (t < WOFF_1) v = W0[t - WOFF_0];
        else if (t < WOFF_2) v = W1[t - WOFF_1];
        else                 v = W2[t - WOFF_2];
        __nv_bfloat16 hi = __float2bfloat16_rn(v);
        g_wh[t] = hi;
        g_wl[t] = __float2bfloat16_rn(v - __bfloat162float(hi));
    }
}

// single-block chunked exclusive scan; re-zeroes g_deg for the next replay
__global__ void scan_kernel() {
    __shared__ int warp_sums[32];
    __shared__ int sCarry;
    const int tid  = threadIdx.x;       // 1024
    const int lane = tid & 31;
    const int wid  = tid >> 5;
    if (tid == 0) sCarry = 0;
    __syncthreads();
    for (int base = 0; base < N_NODES; base += 1024) {
        int idx = base + tid;
        int v = (idx < N_NODES) ? g_deg[idx] : 0;
        if (idx < N_NODES) g_deg[idx] = 0;
        int incl = v;
        #pragma unroll
        for (int d = 1; d < 32; d <<= 1) {
            int t = __shfl_up_sync(0xffffffffu, incl, d);
            if (lane >= d) incl += t;
        }
        if (lane == 31) warp_sums[wid] = incl;
        __syncthreads();
        if (wid == 0) {
            int s = warp_sums[lane];
            #pragma unroll
            for (int d = 1; d < 32; d <<= 1) {
                int t = __shfl_up_sync(0xffffffffu, s, d);
                if (lane >= d) s += t;
            }
            warp_sums[lane] = s;
        }
        __syncthreads();
        int carry = sCarry;
        int woff  = (wid > 0) ? warp_sums[wid - 1] : 0;
        int excl  = carry + woff + incl - v;
        if (idx < N_NODES) { g_rowptr[idx] = excl; g_cursor[idx] = excl; }
        __syncthreads();
        if (tid == 0) sCarry = carry + warp_sums[31];
        __syncthreads();
    }
    if (tid == 0) g_rowptr[N_NODES] = N_EDGES;
}

__global__ void scatter_kernel(const int* __restrict__ src, const int* __restrict__ dst) {
    int e = blockIdx.x * blockDim.x + threadIdx.x;
    if (e < N_EDGES) {
        int d   = dst[e];
        int pos = atomicAdd(&g_cursor[d], 1);
        g_csrc[pos] = src[e];
    }
}

// ---------------- head weight fold: W12 = Wp2 @ Wp1 [40,128] padded to 64 ----------------
__global__ void w12_prep_kernel(const float* __restrict__ Wp1, const float* __restrict__ bp1,
                                const float* __restrict__ Wp2, const float* __restrict__ bp2) {
    __shared__ float wp2s[N_CLS * C_DIM];
    const int tid = threadIdx.x;             // 256
    for (int i = tid; i < N_CLS * C_DIM; i += 256) wp2s[i] = Wp2[i];
    __syncthreads();
    for (int idx = tid; idx < 64 * 128; idx += 256) {
        int o = idx >> 7, k = idx & 127;
        float v = 0.f;
        if (o < N_CLS) {
            #pragma unroll 8
            for (int c = 0; c < C_DIM; c++)
                v += wp2s[o * C_DIM + c] * Wp1[c * 128 + k];
        }
        __nv_bfloat16 hi = __float2bfloat16_rn(v);
        g_wh[WOFF_12 + idx] = hi;
        g_wl[WOFF_12 + idx] = __float2bfloat16_rn(v - __bfloat162float(hi));
    }
    if (tid < 64) {
        float b = 0.f;
        if (tid < N_CLS) {
            for (int c = 0; c < C_DIM; c++) b += wp2s[tid * C_DIM + c] * bp1[c];
            b += bp2[tid];
        }
        g_b12[tid] = b;
    }
}

// ---------------- layer-0 GEMM: fp32 A, 3-term split, BN=64 col-block, PQ out ----------
// grid (1563, 2); colBase = blockIdx.y*64. 8 warps: warp_r=warp&1 (2 strips of 16 within
// 32-row half), warp_c=warp>>1 (4 col groups of 16).
__global__ void __launch_bounds__(256, 3) hmma_gemm3(
    const float* __restrict__ A,
    const __nv_bfloat16* __restrict__ whBase, const __nv_bfloat16* __restrict__ wlBase,
    const float* __restrict__ bias, const float* __restrict__ al)
{
    constexpr int LD = 136;
    constexpr int BN = 64;
    constexpr int CW = 16;                // cols per warp
    constexpr int NT = 2;                 // n8-tiles per warp
    extern __shared__ char smem[];
    const uint32_t su = smem_to_u32(smem);
    const uint32_t OFF_AH = 0;
    const uint32_t OFF_AL = 64 * LD * 2;
    const uint32_t OFF_BH = OFF_AL + 64 * LD * 2;
    const uint32_t OFF_BL = OFF_BH + BN * LD * 2;

    const int tid  = threadIdx.x;
    const int warp = tid >> 5;
    const int lane = tid & 31;
    const int warp_r = warp & 1;
    const int warp_c = warp >> 1;
    const int rowBase = blockIdx.x * 64;
    const int colBase = blockIdx.y * 64;
    const __nv_bfloat16* wh = whBase + (size_t)colBase * 128;
    const __nv_bfloat16* wl = wlBase + (size_t)colBase * 128;

    // ---- stage A (64 rows fp32 -> bf16 hi/lo) ----
    #pragma unroll
    for (int it = 0; it < 8; it++) {
        int i = tid + it * 256;
        int r = i >> 5, c = (i & 31) * 4;
        int grow = rowBase + r;
        float4 v = make_float4(0.f, 0.f, 0.f, 0.f);
        if (grow < N_NODES) v = *(const float4*)(A + (size_t)grow * 128 + c);
        float hx = __bfloat162float(__float2bfloat16_rn(v.x));
        float hy = __bfloat162float(__float2bfloat16_rn(v.y));
        float hz = __bfloat162float(__float2bfloat16_rn(v.z));
        float hw = __bfloat162float(__float2bfloat16_rn(v.w));
        uint2 hi = make_uint2(pack_bf16(v.x, v.y), pack_bf16(v.z, v.w));
        uint2 lo = make_uint2(pack_bf16(v.x - hx, v.y - hy), pack_bf16(v.z - hz, v.w - hw));
        *(uint2*)(smem + OFF_AH + ((size_t)r * LD + c) * 2) = hi;
        *(uint2*)(smem + OFF_AL + ((size_t)r * LD + c) * 2) = lo;
    }
    // ---- stage B (preconverted bf16) ----
    #pragma unroll
    for (int it = 0; it < 4; it++) {
        int i = tid + it * 256;
        int r = i >> 4, c = (i & 15) * 8;
        uint4 vh = *(const uint4*)(wh + (size_t)r * 128 + c);
        uint4 vl = *(const uint4*)(wl + (size_t)r * 128 + c);
        *(uint4*)(smem + OFF_BH + ((size_t)r * LD + c) * 2) = vh;
        *(uint4*)(smem + OFF_BL + ((size_t)r * LD + c) * 2) = vl;
    }
    __syncthreads();

    float acc[2][NT][4];
    #pragma unroll
    for (int s = 0; s < 2; s++)
        #pragma unroll
        for (int n = 0; n < NT; n++)
            #pragma unroll
            for (int j = 0; j < 4; j++) acc[s][n][j] = 0.f;

    uint32_t a_off[2];
    #pragma unroll
    for (int s = 0; s < 2; s++)
        a_off[s] = (uint32_t)(((warp_r * 32 + s * 16 + (lane & 7) + ((lane >> 3) & 1) * 8) * LD
                               + ((lane >> 4) * 8)) * 2);
    const uint32_t b_lane_off =
        (uint32_t)(((warp_c * CW + (lane & 7)) * LD + ((lane >> 3) & 1) * 8) * 2);

    #pragma unroll
    for (int k0 = 0; k0 < 128; k0 += 16) {
        uint32_t ah0[4], al0[4], ah1[4], al1[4];
        ldmatrix_x4(ah0, su + OFF_AH + a_off[0] + k0 * 2);
        ldmatrix_x4(al0, su + OFF_AL + a_off[0] + k0 * 2);
        ldmatrix_x4(ah1, su + OFF_AH + a_off[1] + k0 * 2);
        ldmatrix_x4(al1, su + OFF_AL + a_off[1] + k0 * 2);
        #pragma unroll
        for (int n = 0; n < NT; n++) {
            uint32_t bh[2], bl[2];
            uint32_t boff = b_lane_off + (uint32_t)(n * 8 * LD * 2) + k0 * 2;
            ldmatrix_x2(bh, su + OFF_BH + boff);
            ldmatrix_x2(bl, su + OFF_BL + boff);
            mma_bf16(acc[0][n], ah0, bh);
            mma_bf16(acc[0][n], ah0, bl);
            mma_bf16(acc[0][n], al0, bh);
            mma_bf16(acc[1][n], ah1, bh);
            mma_bf16(acc[1][n], ah1, bl);
            mma_bf16(acc[1][n], al1, bh);
        }
    }

    #pragma unroll
    for (int s = 0; s < 2; s++) {
        const int r0 = rowBase + warp_r * 32 + s * 16 + (lane >> 2);
        const int r1 = r0 + 8;
        #pragma unroll
        for (int n = 0; n < NT; n++) {
            const int col = colBase + warp_c * CW + n * 8 + (lane & 3) * 2;
            const float bx = bias[col], by = bias[col + 1];
            const float a0 = al[col], a1 = al[col + 1];
            if (r0 < N_NODES) {
                float h0v = acc[s][n][0] + bx, h1v = acc[s][n][1] + by;
                float P0 = __expf(a0 * h0v), P1 = __expf(a1 * h1v);
                __half2 x0 = __floats2half2_rn(P0, P0 * h0v);
                __half2 x1 = __floats2half2_rn(P1, P1 * h1v);
                uint2 u; u.x = *(uint32_t*)&x0; u.y = *(uint32_t*)&x1;
                *(uint2*)(g_pq + (size_t)r0 * 128 + col) = u;
            }
            if (r1 < N_NODES) {
                float h0v = acc[s][n][2] + bx, h1v = acc[s][n][3] + by;
                float P0 = __expf(a0 * h0v), P1 = __expf(a1 * h1v);
                __half2 x0 = __floats2half2_rn(P0, P0 * h0v);
                __half2 x1 = __floats2half2_rn(P1, P1 * h1v);
                uint2 u; u.x = *(uint32_t*)&x0; u.y = *(uint32_t*)&x1;
                *(uint2*)(g_pq + (size_t)r1 * 128 + col) = u;
            }
        }
    }
}

// ---------------- layers 1/2 + head GEMM: bf16 A (exact), 2-term, BN=64 ----------------
template <bool PQ_MODE>
__global__ void __launch_bounds__(256, 4) hmma_gemm2(
    const __nv_bfloat16* __restrict__ whBase, const __nv_bfloat16* __restrict__ wlBase,
    const float* __restrict__ bias, const float* __restrict__ al,
    float* __restrict__ Out)
{
    constexpr int LD = 136;
    constexpr int BN = 64;
    constexpr int CW = 16;
    constexpr int NT = 2;
    extern __shared__ char smem[];
    const uint32_t su = smem_to_u32(smem);
    const uint32_t OFF_A  = 0;
    const uint32_t OFF_BH = 64 * LD * 2;
    const uint32_t OFF_BL = OFF_BH + BN * LD * 2;

    const int tid  = threadIdx.x;
    const int warp = tid >> 5;
    const int lane = tid & 31;
    const int warp_r = warp & 1;
    const int warp_c = warp >> 1;
    const int rowBase = blockIdx.x * 64;
    const int colBase = blockIdx.y * 64;
    const __nv_bfloat16* wh = whBase + (size_t)colBase * 128;
    const __nv_bfloat16* wl = wlBase + (size_t)colBase * 128;

    // ---- stage A (64 rows bf16, pure copies) ----
    #pragma unroll
    for (int it = 0; it < 4; it++) {
        int i = tid + it * 256;               // 64*16 = 1024 uint4 slots
        int r = i >> 4, c = (i & 15) * 8;
        int grow = rowBase + r;
        uint4 v = make_uint4(0u, 0u, 0u, 0u);
        if (grow < N_NODES) v = *(const uint4*)(g_hb + (size_t)grow * 128 + c);
        *(uint4*)(smem + OFF_A + ((size_t)r * LD + c) * 2) = v;
    }
    // ---- stage B ----
    #pragma unroll
    for (int it = 0; it < 4; it++) {
        int i = tid + it * 256;
        int r = i >> 4, c = (i & 15) * 8;
        uint4 vh = *(const uint4*)(wh + (size_t)r * 128 + c);
        uint4 vl = *(const uint4*)(wl + (size_t)r * 128 + c);
        *(uint4*)(smem + OFF_BH + ((size_t)r * LD + c) * 2) = vh;
        *(uint4*)(smem + OFF_BL + ((size_t)r * LD + c) * 2) = vl;
    }
    __syncthreads();

    float acc[2][NT][4];
    #pragma unroll
    for (int s = 0; s < 2; s++)
        #pragma unroll
        for (int n = 0; n < NT; n++)
            #pragma unroll
            for (int j = 0; j < 4; j++) acc[s][n][j] = 0.f;

    uint32_t a_off[2];
    #pragma unroll
    for (int s = 0; s < 2; s++)
        a_off[s] = (uint32_t)(((warp_r * 32 + s * 16 + (lane & 7) + ((lane >> 3) & 1) * 8) * LD
                               + ((lane >> 4) * 8)) * 2);
    const uint32_t b_lane_off =
        (uint32_t)(((warp_c * CW + (lane & 7)) * LD + ((lane >> 3) & 1) * 8) * 2);

    #pragma unroll
    for (int k0 = 0; k0 < 128; k0 += 16) {
        uint32_t a0[4], a1[4];
        ldmatrix_x4(a0, su + OFF_A + a_off[0] + k0 * 2);
        ldmatrix_x4(a1, su + OFF_A + a_off[1] + k0 * 2);
        #pragma unroll
        for (int n = 0; n < NT; n++) {
            uint32_t bh[2], bl[2];
            uint32_t boff = b_lane_off + (uint32_t)(n * 8 * LD * 2) + k0 * 2;
            ldmatrix_x2(bh, su + OFF_BH + boff);
            ldmatrix_x2(bl, su + OFF_BL + boff);
            mma_bf16(acc[0][n], a0, bh);
            mma_bf16(acc[0][n], a0, bl);
            mma_bf16(acc[1][n], a1, bh);
            mma_bf16(acc[1][n], a1, bl);
        }
    }

    #pragma unroll
    for (int s = 0; s < 2; s++) {
        const int r0 = rowBase + warp_r * 32 + s * 16 + (lane >> 2);
        const int r1 = r0 + 8;
        #pragma unroll
        for (int n = 0; n < NT; n++) {
            const int col = colBase + warp_c * CW + n * 8 + (lane & 3) * 2;
            const float bx = bias[col], by = bias[col + 1];
            if (PQ_MODE) {
                const float a0 = al[col], a1 = al[col + 1];
                if (r0 < N_NODES) {
                    float h0v = acc[s][n][0] + bx, h1v = acc[s][n][1] + by;
                    float P0 = __expf(a0 * h0v), P1 = __expf(a1 * h1v);
                    __half2 x0 = __floats2half2_rn(P0, P0 * h0v);
                    __half2 x1 = __floats2half2_rn(P1, P1 * h1v);
                    uint2 u; u.x = *(uint32_t*)&x0; u.y = *(uint32_t*)&x1;
                    *(uint2*)(g_pq + (size_t)r0 * 128 + col) = u;
                }
                if (r1 < N_NODES) {
                    float h0v = acc[s][n][2] + bx, h1v = acc[s][n][3] + by;
                    float P0 = __expf(a0 * h0v), P1 = __expf(a1 * h1v);
                    __half2 x0 = __floats2half2_rn(P0, P0 * h0v);
                    __half2 x1 = __floats2half2_rn(P1, P1 * h1v);
                    uint2 u; u.x = *(uint32_t*)&x0; u.y = *(uint32_t*)&x1;
                    *(uint2*)(g_pq + (size_t)r1 * 128 + col) = u;
                }
            } else {
                if (r0 < N_NODES)
                    *(float2*)(Out + (size_t)r0 * 64 + col) =
                        make_float2(acc[s][n][0] + bx, acc[s][n][1] + by);
                if (r1 < N_NODES)
                    *(float2*)(Out + (size_t)r1 * 64 + col) =
                        make_float2(acc[s][n][2] + bx, acc[s][n][3] + by);
            }
        }
    }
}

// ---------------- aggregation: warp/node, independent __ldg + 8-deep pipeline -----------
// writes h (relu'd attention output) as bf16 into g_hb
__global__ void gat_agg_sum() {
    const int node = blockIdx.x * (blockDim.x >> 5) + (threadIdx.x >> 5);
    if (node >= N_NODES) return;
    const int lane = threadIdx.x & 31;
    const int beg = g_rowptr[node];
    const int end = g_rowptr[node + 1];

    float S0=0.f,S1=0.f,S2=0.f,S3=0.f;
    float A0=0.f,A1=0.f,A2=0.f,A3=0.f;

    const uint4* __restrict__ pq = (const uint4*)g_pq;
    #define ACCUM(v) do { \
        __half2 p0 = *(__half2*)&(v).x, p1 = *(__half2*)&(v).y; \
        __half2 p2 = *(__half2*)&(v).z, p3 = *(__half2*)&(v).w; \
        float2 f0 = __half22float2(p0), f1 = __half22float2(p1); \
        float2 f2 = __half22float2(p2), f3 = __half22float2(p3); \
        S0 += f0.x; A0 += f0.y;  S1 += f1.x; A1 += f1.y; \
        S2 += f2.x; A2 += f2.y;  S3 += f3.x; A3 += f3.y; \
    } while (0)

    int e = beg;
    for (; e + 8 <= end; e += 8) {
        int s0 = __ldg(&g_csrc[e + 0]);
        int s1 = __ldg(&g_csrc[e + 1]);
        int s2 = __ldg(&g_csrc[e + 2]);
        int s3 = __ldg(&g_csrc[e + 3]);
        int s4 = __ldg(&g_csrc[e + 4]);
        int s5 = __ldg(&g_csrc[e + 5]);
        int s6 = __ldg(&g_csrc[e + 6]);
        int s7 = __ldg(&g_csrc[e + 7]);
        uint4 v0 = pq[(size_t)s0 * 32 + lane];
        uint4 v1 = pq[(size_t)s1 * 32 + lane];
        uint4 v2 = pq[(size_t)s2 * 32 + lane];
        uint4 v3 = pq[(size_t)s3 * 32 + lane];
        uint4 v4 = pq[(size_t)s4 * 32 + lane];
        uint4 v5 = pq[(size_t)s5 * 32 + lane];
        uint4 v6 = pq[(size_t)s6 * 32 + lane];
        uint4 v7 = pq[(size_t)s7 * 32 + lane];
        ACCUM(v0); ACCUM(v1); ACCUM(v2); ACCUM(v3);
        ACCUM(v4); ACCUM(v5); ACCUM(v6); ACCUM(v7);
    }
    for (; e + 2 <= end; e += 2) {
        int s0 = __ldg(&g_csrc[e + 0]);
        int s1 = __ldg(&g_csrc[e + 1]);
        uint4 v0 = pq[(size_t)s0 * 32 + lane];
        uint4 v1 = pq[(size_t)s1 * 32 + lane];
        ACCUM(v0); ACCUM(v1);
    }
    for (; e < end; e++) {
        int s = __ldg(&g_csrc[e]);
        uint4 v = pq[(size_t)s * 32 + lane];
        ACCUM(v);
    }
    #undef ACCUM

    float ox = fmaxf(A0 / (S0 + EPS_F), 0.f);
    float oy = fmaxf(A1 / (S1 + EPS_F), 0.f);
    float oz = fmaxf(A2 / (S2 + EPS_F), 0.f);
    float ow = fmaxf(A3 / (S3 + EPS_F), 0.f);
    uint2 u;
    u.x = pack_bf16(ox, oy);
    u.y = pack_bf16(oz, ow);
    *(uint2*)(g_hb + (size_t)node * HCDIM + lane * 4) = u;
}

// ---------------- log_softmax over 40 classes (reads padded [N,64] logits) ------------
__global__ void logsoftmax_kernel(float* __restrict__ out) {
    const int node = blockIdx.x * blockDim.x + threadIdx.x;
    if (node >= N_NODES) return;
    const float* row = g_t + (size_t)node * 64;
    float l[N_CLS];
    #pragma unroll
    for (int j = 0; j < N_CLS; j += 4) {
        float4 v = *(const float4*)(row + j);
        l[j] = v.x; l[j+1] = v.y; l[j+2] = v.z; l[j+3] = v.w;
    }
    float m = l[0];
    #pragma unroll
    for (int j = 1; j < N_CLS; j++) m = fmaxf(m, l[j]);
    float se = 0.f;
    #pragma unroll
    for (int j = 0; j < N_CLS; j++) se += __expf(l[j] - m);
    float lse = m + __logf(se);
    float* orow = out + (size_t)node * N_CLS;
    #pragma unroll
    for (int j = 0; j < N_CLS; j += 4) {
        float4 v = make_float4(l[j] - lse, l[j+1] - lse, l[j+2] - lse, l[j+3] - lse);
        *(float4*)(orow + j) = v;
    }
}

// ---------------- launch ----------------
extern "C" void kernel_launch(void* const* d_in, const int* in_sizes, int n_in,
                              void* d_out, int out_size) {
    const float* x   = (const float*)d_in[0];
    const int*   ei  = (const int*)  d_in[1];
    const float* W0  = (const float*)d_in[2];
    const float* b0  = (const float*)d_in[3];
    const float* al0 = (const float*)d_in[4];
    const float* W1  = (const float*)d_in[6];
    const float* b1  = (const float*)d_in[7];
    const float* al1 = (const float*)d_in[8];
    const float* W2  = (const float*)d_in[10];
    const float* b2  = (const float*)d_in[11];
    const float* al2 = (const float*)d_in[12];
    const float* Wp1 = (const float*)d_in[14];
    const float* bp1 = (const float*)d_in[15];
    const float* Wp2 = (const float*)d_in[16];
    const float* bp2 = (const float*)d_in[17];
    float* out = (float*)d_out;

    const int* srcv = ei;
    const int* dstv = ei + N_EDGES;

    float *tb, *b12;
    __nv_bfloat16 *wh, *wl;
    cudaGetSymbolAddress((void**)&tb, g_t);
    cudaGetSymbolAddress((void**)&wh, g_wh);
    cudaGetSymbolAddress((void**)&wl, g_wl);
    cudaGetSymbolAddress((void**)&b12, g_b12);

    constexpr int LD = 136;
    const int SMEM3 = (2 * 64 * LD + 2 * 64 * LD) * 2;      // 69632
    const int SMEM2 = (64 * LD + 2 * 64 * LD) * 2;          // 52224
    cudaFuncSetAttribute((const void*)hmma_gemm3,
                         cudaFuncAttributeMaxDynamicSharedMemorySize, SMEM3);
    cudaFuncSetAttribute((const void*)hmma_gemm2<true>,
                         cudaFuncAttributeMaxDynamicSharedMemorySize, SMEM2);
    cudaFuncSetAttribute((const void*)hmma_gemm2<false>,
                         cudaFuncAttributeMaxDynamicSharedMemorySize, SMEM2);

    // CSR + weight conversion
    count_deg_convw_kernel<<<(N_EDGES + 255) / 256, 256>>>(dstv, W0, W1, W2);
    scan_kernel<<<1, 1024>>>();
    scatter_kernel<<<(N_EDGES + 255) / 256, 256>>>(srcv, dstv);

    const dim3 g2((N_NODES + 63) / 64, 2);
    const dim3 g1((N_NODES + 63) / 64, 1);
    const int aggGrid = (N_NODES + 7) / 8;

    // layer 0 (launch #4 -> ncu target)
    hmma_gemm3<<<g2, 256, SMEM3>>>(x, wh + WOFF_0, wl + WOFF_0, b0, al0);
    w12_prep_kernel<<<1, 256>>>(Wp1, bp1, Wp2, bp2);
    gat_agg_sum<<<aggGrid, 256>>>();
    // layer 1
    hmma_gemm2<true><<<g2, 256, SMEM2>>>(wh + WOFF_1, wl + WOFF_1, b1, al1, nullptr);
    gat_agg_sum<<<aggGrid, 256>>>();
    // layer 2
    hmma_gemm2<true><<<g2, 256, SMEM2>>>(wh + WOFF_2, wl + WOFF_2, b2, al2, nullptr);
    gat_agg_sum<<<aggGrid, 256>>>();
    // head: fused (Wp2@Wp1) GEMM -> padded logits, then log_softmax
    hmma_gemm2<false><<<g1, 256, SMEM2>>>(wh + WOFF_12, wl + WOFF_12, b12, nullptr, tb);
    logsoftmax_kernel<<<(N_NODES + 255) / 256, 256>>>(out);
}